// round 3
// baseline (speedup 1.0000x reference)
#include <cuda_runtime.h>
#include <cuda_bf16.h>
#include <cstdint>
#include <cstddef>

#define B_ 64
#define T_ 2048
#define D_ 128
#define H_ 256
#define G4_ 1024
#define NCOL_ 2048   // fwd 4H | bwd 4H

// Scratch: device globals (allocation-free rule)
static __device__ float g_xw[(size_t)B_ * T_ * NCOL_];   // [b*T+t][2048]  ~1.07 GB
static __device__ float g_h [(size_t)2 * B_ * T_ * H_];  // [dir][b][t][h] ~268 MB

__device__ __forceinline__ float fsig(float x) {
    // exact IEEE divide: handles exp overflow to +inf -> 0 correctly
    return 1.0f / (1.0f + __expf(-x));
}
__device__ __forceinline__ float ftanh_(float x) {
    return 2.0f / (1.0f + __expf(-2.0f * x)) - 1.0f;
}
__device__ __forceinline__ uint32_t smem_u32(const void* p) {
    uint32_t a;
    asm("{ .reg .u64 t; cvta.to.shared.u64 t, %1; cvt.u32.u64 %0, t; }" : "=r"(a) : "l"(p));
    return a;
}

// ---------------------------------------------------------------------------
// Phase A: g_xw[m][0:1024]=x@k_fwd+b_fwd ; g_xw[m][1024:2048]=x@k_bwd+b_bwd
// BM=BN=128, BK=16, 256 threads, 8x8 per-thread tile.
// ---------------------------------------------------------------------------
__global__ __launch_bounds__(256) void gemm_xw_kernel(
    const float* __restrict__ x,
    const float* __restrict__ kf, const float* __restrict__ bf,
    const float* __restrict__ kb, const float* __restrict__ bb)
{
    __shared__ float As[16][132];
    __shared__ float Bs[16][132];
    const int ntile = blockIdx.x;          // 0..15 (8 fwd, 8 bwd)
    const int mtile = blockIdx.y;          // 0..1023
    const float* w    = (ntile < 8) ? kf : kb;
    const float* bias = (ntile < 8) ? bf : bb;
    const int n0 = (ntile & 7) * 128;      // col within direction
    const int m0 = mtile * 128;
    const int tid = threadIdx.x;
    const int ty = tid >> 4, tx = tid & 15;

    float acc[8][8];
#pragma unroll
    for (int i = 0; i < 8; i++)
#pragma unroll
        for (int j = 0; j < 8; j++) acc[i][j] = 0.f;

    const int li = tid >> 2, lj = (tid & 3) << 2;
    const int bk = tid >> 5, bn = (tid & 31) << 2;

    for (int k0 = 0; k0 < D_; k0 += 16) {
        float4 a0 = *(const float4*)&x[(size_t)(m0 + li) * D_ + k0 + lj];
        float4 a1 = *(const float4*)&x[(size_t)(m0 + 64 + li) * D_ + k0 + lj];
        float4 b0 = *(const float4*)&w[(size_t)(k0 + bk) * G4_ + n0 + bn];
        float4 b1 = *(const float4*)&w[(size_t)(k0 + 8 + bk) * G4_ + n0 + bn];
        __syncthreads();
        As[lj + 0][li] = a0.x; As[lj + 1][li] = a0.y; As[lj + 2][li] = a0.z; As[lj + 3][li] = a0.w;
        As[lj + 0][64 + li] = a1.x; As[lj + 1][64 + li] = a1.y; As[lj + 2][64 + li] = a1.z; As[lj + 3][64 + li] = a1.w;
        *(float4*)&Bs[bk][bn]     = b0;
        *(float4*)&Bs[bk + 8][bn] = b1;
        __syncthreads();
#pragma unroll
        for (int k = 0; k < 16; k++) {
            float a[8], bv[8];
            *(float4*)&a[0]  = *(const float4*)&As[k][ty * 8];
            *(float4*)&a[4]  = *(const float4*)&As[k][ty * 8 + 4];
            *(float4*)&bv[0] = *(const float4*)&Bs[k][tx * 8];
            *(float4*)&bv[4] = *(const float4*)&Bs[k][tx * 8 + 4];
#pragma unroll
            for (int i = 0; i < 8; i++)
#pragma unroll
                for (int j = 0; j < 8; j++)
                    acc[i][j] += a[i] * bv[j];
        }
    }

    const int gcol0 = ntile * 128 + tx * 8;
    float bv0[8];
#pragma unroll
    for (int j = 0; j < 8; j++) bv0[j] = bias[n0 + tx * 8 + j];
#pragma unroll
    for (int i = 0; i < 8; i++) {
        size_t row = (size_t)(m0 + ty * 8 + i);
        float4 o0 = make_float4(acc[i][0] + bv0[0], acc[i][1] + bv0[1],
                                acc[i][2] + bv0[2], acc[i][3] + bv0[3]);
        float4 o1 = make_float4(acc[i][4] + bv0[4], acc[i][5] + bv0[5],
                                acc[i][6] + bv0[6], acc[i][7] + bv0[7]);
        *(float4*)&g_xw[row * NCOL_ + gcol0]     = o0;
        *(float4*)&g_xw[row * NCOL_ + gcol0 + 4] = o1;
    }
}

// ---------------------------------------------------------------------------
// Phase B: recurrence. Grid (8,16), cluster (8,1,1).
//   blockIdx.y: bit0 = dir, bits1.. = batch group (8 rows)
//   blockIdx.x = cluster rank = cell group: cells [rank*32, rank*32+32),
//   local gate cols c=0..127: gate=c>>5, cell=rank*32+(c&31)
// R slice (256 k x 128 cols) resident in smem; h (8x256) exchanged via
// DSMEM stores, double buffered; one cluster barrier per step.
// ---------------------------------------------------------------------------
#define RSTR 260
#define SMEM_B_BYTES ((128 * RSTR + 2 * 8 * 256 + 1024 + 1024) * 4)

extern __shared__ float smemB[];

__global__ __launch_bounds__(256, 1) __cluster_dims__(8, 1, 1)
void lstm_rec_kernel(const float* __restrict__ rf, const float* __restrict__ rb)
{
    float* R_s  = smemB;                       // [c=0..127][k=0..255], stride RSTR
    float* h_sm = smemB + 128 * RSTR;          // [2][8][256]
    float* z_s  = h_sm + 2 * 8 * 256;          // [8][128]  (kh=0 partial + xw)
    float* z2_s = z_s + 1024;                  // [8][128]  (kh=1 partial)

    const int rank  = blockIdx.x;
    const int dir   = blockIdx.y & 1;
    const int bg    = blockIdx.y >> 1;
    const int b0    = bg * 8;
    const int cell0 = rank * 32;
    const int tid   = threadIdx.x;
    const float* rec = dir ? rb : rf;

    // Load R slice: R_s[c][k] = rec[k][gate(c)*256 + cell0 + (c&31)]
    {
        const int c = tid & 127, kh2 = tid >> 7;
        const int gcol = ((c >> 5) << 8) + cell0 + (c & 31);
        for (int k = kh2 * 128; k < kh2 * 128 + 128; k++)
            R_s[c * RSTR + k] = rec[(size_t)k * G4_ + gcol];
    }
    for (int i = tid; i < 2 * 8 * 256; i += 256) h_sm[i] = 0.f;

    const int gr  = tid >> 5;        // gate-phase: row 0..7
    const int gc  = tid & 31;        // gate-phase: cell within group
    const int col = tid & 127;       // gemm-phase: local gate column
    const int kh  = tid >> 7;        // gemm-phase: k half (0/1)
    const int gate = col >> 5;
    const int gcolG = dir * 1024 + gate * 256 + cell0 + (col & 31);
    const uint32_t hbase = smem_u32(h_sm);

    float c_reg = 0.f;

    __syncthreads();
    asm volatile("barrier.cluster.arrive.aligned;" ::: "memory");
    asm volatile("barrier.cluster.wait.aligned;" ::: "memory");

    for (int s = 0; s < T_; s++) {
        const int t = dir ? (T_ - 1 - s) : s;
        const int buf = s & 1;
        const float* hb = h_sm + buf * 2048 + kh * 128;

        float xw[8];
        if (kh == 0) {
#pragma unroll
            for (int r = 0; r < 8; r++)
                xw[r] = g_xw[((size_t)(b0 + r) * T_ + t) * NCOL_ + gcolG];
        }

        float acc[8] = {0.f, 0.f, 0.f, 0.f, 0.f, 0.f, 0.f, 0.f};
        const float* Rp = R_s + col * RSTR + kh * 128;
#pragma unroll 8
        for (int kk = 0; kk < 128; kk += 4) {
            float4 rv = *(const float4*)(Rp + kk);
#pragma unroll
            for (int r = 0; r < 8; r++) {
                float4 hv4 = *(const float4*)(hb + r * 256 + kk);
                acc[r] += hv4.x * rv.x;
                acc[r] += hv4.y * rv.y;
                acc[r] += hv4.z * rv.z;
                acc[r] += hv4.w * rv.w;
            }
        }
        if (kh == 0) {
#pragma unroll
            for (int r = 0; r < 8; r++) z_s[r * 128 + col] = acc[r] + xw[r];
        } else {
#pragma unroll
            for (int r = 0; r < 8; r++) z2_s[r * 128 + col] = acc[r];
        }
        __syncthreads();

        // Gate + state update: this thread owns (row gr, cell cell0+gc)
        const int zb = gr * 128 + gc;
        float iv = z_s[zb]      + z2_s[zb];
        float fv = z_s[zb + 32] + z2_s[zb + 32];
        float gv = z_s[zb + 64] + z2_s[zb + 64];
        float ov = z_s[zb + 96] + z2_s[zb + 96];
        c_reg = fsig(fv) * c_reg + fsig(iv) * ftanh_(gv);
        const float hv = fsig(ov) * ftanh_(c_reg);

        g_h[(((size_t)dir * B_ + (b0 + gr)) * T_ + t) * H_ + cell0 + gc] = hv;

        // Push h to all 8 cluster CTAs (next-step buffer)
        const uint32_t off = hbase + (uint32_t)(((buf ^ 1) * 2048 + gr * 256 + cell0 + gc) * 4);
#pragma unroll
        for (int dst = 0; dst < 8; dst++) {
            uint32_t raddr;
            asm volatile("mapa.shared::cluster.u32 %0, %1, %2;" : "=r"(raddr) : "r"(off), "r"(dst));
            asm volatile("st.shared::cluster.f32 [%0], %1;" :: "r"(raddr), "f"(hv));
        }
        // release/acquire: orders the DSMEM stores; also a full intra-CTA barrier
        asm volatile("barrier.cluster.arrive.aligned;" ::: "memory");
        asm volatile("barrier.cluster.wait.aligned;" ::: "memory");
    }
}

// ---------------------------------------------------------------------------
// Phase C: attention pooling. One block (256 thr) per batch row.
// ---------------------------------------------------------------------------
__global__ __launch_bounds__(256) void attn_kernel(const float* __restrict__ att_w,
                                                   float* __restrict__ out)
{
    __shared__ float logits[T_];
    __shared__ float aw[H_];
    __shared__ float red[8];
    const int b = blockIdx.x;
    const int tid = threadIdx.x;
    const int warp = tid >> 5, lane = tid & 31;

    for (int i = tid; i < H_; i += 256) aw[i] = att_w[i];
    __syncthreads();

    const float* hf = g_h + (size_t)b * T_ * H_;
    const float* hbp = g_h + ((size_t)B_ + b) * T_ * H_;

    // Pass 1: logits[t] = att_w . tanh(hf+hb), one warp per t (strided)
    for (int t = warp; t < T_; t += 8) {
        float s = 0.f;
        const float* pf = hf + (size_t)t * H_;
        const float* pb = hbp + (size_t)t * H_;
#pragma unroll
        for (int j = 0; j < 8; j++) {
            int c = lane + 32 * j;
            s += aw[c] * ftanh_(pf[c] + pb[c]);
        }
#pragma unroll
        for (int o = 16; o > 0; o >>= 1) s += __shfl_xor_sync(0xFFFFFFFFu, s, o);
        if (lane == 0) logits[t] = s;
    }
    __syncthreads();

    // Block-reduce max
    float m = -1e30f;
    for (int t = tid; t < T_; t += 256) m = fmaxf(m, logits[t]);
#pragma unroll
    for (int o = 16; o > 0; o >>= 1) m = fmaxf(m, __shfl_xor_sync(0xFFFFFFFFu, m, o));
    if (lane == 0) red[warp] = m;
    __syncthreads();
    float mg = red[0];
#pragma unroll
    for (int i = 1; i < 8; i++) mg = fmaxf(mg, red[i]);
    __syncthreads();

    // exp in place + block-reduce sum
    float ssum = 0.f;
    for (int t = tid; t < T_; t += 256) {
        float e = __expf(logits[t] - mg);
        logits[t] = e;
        ssum += e;
    }
#pragma unroll
    for (int o = 16; o > 0; o >>= 1) ssum += __shfl_xor_sync(0xFFFFFFFFu, ssum, o);
    if (lane == 0) red[warp] = ssum;
    __syncthreads();
    float stot = 0.f;
#pragma unroll
    for (int i = 0; i < 8; i++) stot += red[i];
    const float inv = 1.0f / stot;
    __syncthreads();

    // Pass 2: r[col] = sum_t a[t] * (hf+hb)[t][col], col = tid
    const int col = tid;
    float r = 0.f;
    for (int t = 0; t < T_; t++) {
        r += logits[t] * (hf[(size_t)t * H_ + col] + hbp[(size_t)t * H_ + col]);
    }
    out[b * H_ + col] = ftanh_(r * inv);
}

// ---------------------------------------------------------------------------
extern "C" void kernel_launch(void* const* d_in, const int* in_sizes, int n_in,
                              void* d_out, int out_size) {
    (void)in_sizes; (void)n_in; (void)out_size;
    const float* x     = (const float*)d_in[0];
    const float* k_fwd = (const float*)d_in[1];
    const float* r_fwd = (const float*)d_in[2];
    const float* b_fwd = (const float*)d_in[3];
    const float* k_bwd = (const float*)d_in[4];
    const float* r_bwd = (const float*)d_in[5];
    const float* b_bwd = (const float*)d_in[6];
    const float* att_w = (const float*)d_in[7];
    float* out = (float*)d_out;

    gemm_xw_kernel<<<dim3(16, 1024), 256>>>(x, k_fwd, b_fwd, k_bwd, b_bwd);

    cudaFuncSetAttribute(lstm_rec_kernel,
                         cudaFuncAttributeMaxDynamicSharedMemorySize, SMEM_B_BYTES);
    lstm_rec_kernel<<<dim3(8, 16), 256, SMEM_B_BYTES>>>(r_fwd, r_bwd);

    attn_kernel<<<B_, 256>>>(att_w, out);
}

// round 4
// speedup vs baseline: 1.2973x; 1.2973x over previous
#include <cuda_runtime.h>
#include <cuda_bf16.h>
#include <cstdint>
#include <cstddef>

#define B_ 64
#define T_ 2048
#define D_ 128
#define H_ 256
#define G4_ 1024
#define NCOL_ 2048   // fwd 4H | bwd 4H

// Scratch: device globals (allocation-free rule)
static __device__ float g_xw[(size_t)B_ * T_ * NCOL_];   // [b*T+t][2048]  ~1.07 GB
static __device__ float g_h [(size_t)2 * B_ * T_ * H_];  // [dir][b][t][h] ~268 MB

__device__ __forceinline__ float fsig(float x) {
    return 1.0f / (1.0f + __expf(-x));
}
__device__ __forceinline__ float ftanh_(float x) {
    return 2.0f / (1.0f + __expf(-2.0f * x)) - 1.0f;
}
__device__ __forceinline__ uint32_t smem_u32(const void* p) {
    uint32_t a;
    asm("{ .reg .u64 t; cvta.to.shared.u64 t, %1; cvt.u32.u64 %0, t; }" : "=r"(a) : "l"(p));
    return a;
}

// ---------------------------------------------------------------------------
// Phase A: g_xw[m][0:1024]=x@k_fwd+b_fwd ; g_xw[m][1024:2048]=x@k_bwd+b_bwd
// BM=BN=128, BK=16, 256 threads, 8x8 per-thread tile. (unchanged, ~1.5ms)
// ---------------------------------------------------------------------------
__global__ __launch_bounds__(256) void gemm_xw_kernel(
    const float* __restrict__ x,
    const float* __restrict__ kf, const float* __restrict__ bf,
    const float* __restrict__ kb, const float* __restrict__ bb)
{
    __shared__ float As[16][132];
    __shared__ float Bs[16][132];
    const int ntile = blockIdx.x;          // 0..15 (8 fwd, 8 bwd)
    const int mtile = blockIdx.y;          // 0..1023
    const float* w    = (ntile < 8) ? kf : kb;
    const float* bias = (ntile < 8) ? bf : bb;
    const int n0 = (ntile & 7) * 128;
    const int m0 = mtile * 128;
    const int tid = threadIdx.x;
    const int ty = tid >> 4, tx = tid & 15;

    float acc[8][8];
#pragma unroll
    for (int i = 0; i < 8; i++)
#pragma unroll
        for (int j = 0; j < 8; j++) acc[i][j] = 0.f;

    const int li = tid >> 2, lj = (tid & 3) << 2;
    const int bk = tid >> 5, bn = (tid & 31) << 2;

    for (int k0 = 0; k0 < D_; k0 += 16) {
        float4 a0 = *(const float4*)&x[(size_t)(m0 + li) * D_ + k0 + lj];
        float4 a1 = *(const float4*)&x[(size_t)(m0 + 64 + li) * D_ + k0 + lj];
        float4 b0 = *(const float4*)&w[(size_t)(k0 + bk) * G4_ + n0 + bn];
        float4 b1 = *(const float4*)&w[(size_t)(k0 + 8 + bk) * G4_ + n0 + bn];
        __syncthreads();
        As[lj + 0][li] = a0.x; As[lj + 1][li] = a0.y; As[lj + 2][li] = a0.z; As[lj + 3][li] = a0.w;
        As[lj + 0][64 + li] = a1.x; As[lj + 1][64 + li] = a1.y; As[lj + 2][64 + li] = a1.z; As[lj + 3][64 + li] = a1.w;
        *(float4*)&Bs[bk][bn]     = b0;
        *(float4*)&Bs[bk + 8][bn] = b1;
        __syncthreads();
#pragma unroll
        for (int k = 0; k < 16; k++) {
            float a[8], bv[8];
            *(float4*)&a[0]  = *(const float4*)&As[k][ty * 8];
            *(float4*)&a[4]  = *(const float4*)&As[k][ty * 8 + 4];
            *(float4*)&bv[0] = *(const float4*)&Bs[k][tx * 8];
            *(float4*)&bv[4] = *(const float4*)&Bs[k][tx * 8 + 4];
#pragma unroll
            for (int i = 0; i < 8; i++)
#pragma unroll
                for (int j = 0; j < 8; j++)
                    acc[i][j] += a[i] * bv[j];
        }
    }

    const int gcol0 = ntile * 128 + tx * 8;
    float bv0[8];
#pragma unroll
    for (int j = 0; j < 8; j++) bv0[j] = bias[n0 + tx * 8 + j];
#pragma unroll
    for (int i = 0; i < 8; i++) {
        size_t row = (size_t)(m0 + ty * 8 + i);
        float4 o0 = make_float4(acc[i][0] + bv0[0], acc[i][1] + bv0[1],
                                acc[i][2] + bv0[2], acc[i][3] + bv0[3]);
        float4 o1 = make_float4(acc[i][4] + bv0[4], acc[i][5] + bv0[5],
                                acc[i][6] + bv0[6], acc[i][7] + bv0[7]);
        *(float4*)&g_xw[row * NCOL_ + gcol0]     = o0;
        *(float4*)&g_xw[row * NCOL_ + gcol0 + 4] = o1;
    }
}

// ---------------------------------------------------------------------------
// Phase B: recurrence. Grid (8,16), cluster (8,1,1), 512 threads.
//   blockIdx.y: bit0 = dir, bits1.. = batch group (8 rows)
//   blockIdx.x = cluster rank: cells [rank*32, rank*32+32)
//     -> local gate cols c=0..127: gate=c>>5, cell=rank*32+(c&31)
// Layouts (all transposed for 3-LDS/32-FFMA inner loop):
//   R_s[k][c]   k=0..255, c=0..127, row stride 132 (conflict-free float4)
//   Hb[2][k][r] k=cell 0..255, r=row 0..7 (two float4 broadcasts per k)
//   z_s[slice 0..15][r][c] partials, stride 128
//   stage[r][cg] stride 36 (conflict-free transposed read for push)
// ---------------------------------------------------------------------------
#define RS2 132
#define NSL 16
#define SMEM_B_BYTES ((256 * RS2 + 2 * 256 * 8 + NSL * 8 * 128 + 8 * 36) * 4)

extern __shared__ float smemB[];

__global__ __launch_bounds__(512, 1) __cluster_dims__(8, 1, 1)
void lstm_rec_kernel(const float* __restrict__ rf, const float* __restrict__ rb)
{
    float* R_s   = smemB;                     // [256][132]
    float* Hb    = smemB + 256 * RS2;         // [2][256][8]
    float* z_s   = Hb + 2 * 256 * 8;          // [16][8][128]
    float* stage = z_s + NSL * 8 * 128;       // [8][36]

    const int rank  = blockIdx.x;
    const int dir   = blockIdx.y & 1;
    const int bg    = blockIdx.y >> 1;
    const int b0    = bg * 8;
    const int cell0 = rank * 32;
    const int tid   = threadIdx.x;
    const float* rec = dir ? rb : rf;

    // Load R slice transposed: R_s[k][c] = rec[k][gate(c)*256 + cell0 + (c&31)]
    for (int idx = tid; idx < 256 * 128; idx += 512) {
        const int k = idx >> 7, c = idx & 127;
        const int gcol = ((c >> 5) << 8) + cell0 + (c & 31);
        R_s[k * RS2 + c] = rec[(size_t)k * G4_ + gcol];
    }
    for (int i = tid; i < 2 * 256 * 8; i += 512) Hb[i] = 0.f;

    const int lane = tid & 31;
    const int ks   = tid >> 5;          // k-slice 0..15, k in [ks*16, ks*16+16)
    const int col4 = lane * 4;          // this thread's 4 gate columns
    // gate-phase mapping (threads 0..255): row gr, cell cell0+gc
    const int gr = (tid >> 5) & 7;
    const int gc = tid & 31;
    // push-phase mapping (all 512): j linear over (cell-in-group, row)
    const int j  = tid & 255;
    const int pr = j & 7, pcg = j >> 3;
    const int dst0 = (tid < 256) ? 0 : 4;
    const uint32_t hbase = smem_u32(Hb);

    float c_reg = 0.f;

    __syncthreads();
    asm volatile("barrier.cluster.arrive.aligned;" ::: "memory");
    asm volatile("barrier.cluster.wait.aligned;" ::: "memory");

    for (int s = 0; s < T_; s++) {
        const int t = dir ? (T_ - 1 - s) : s;
        const int buf = s & 1;

        // Early xw loads (hide DRAM latency behind the gemm)
        float xw0, xw1, xw2, xw3;
        if (tid < 256) {
            const float* xp = g_xw + ((size_t)(b0 + gr) * T_ + t) * NCOL_
                            + dir * 1024 + cell0 + gc;
            xw0 = xp[0]; xw1 = xp[256]; xw2 = xp[512]; xw3 = xp[768];
        }

        // GEMM: acc[r][c] over 16 k, 3 LDS.128 + 32 FFMA per k
        float4 acc[8];
#pragma unroll
        for (int r = 0; r < 8; r++) acc[r] = make_float4(0.f, 0.f, 0.f, 0.f);
        const float* Rp = R_s + (ks * 16) * RS2 + col4;
        const float* Hp = Hb + buf * 2048 + (ks * 16) * 8;
#pragma unroll
        for (int kk = 0; kk < 16; kk++) {
            float4 rv = *(const float4*)(Rp + kk * RS2);
            float4 ha = *(const float4*)(Hp + kk * 8);
            float4 hc = *(const float4*)(Hp + kk * 8 + 4);
            float hh[8];
            *(float4*)&hh[0] = ha;
            *(float4*)&hh[4] = hc;
#pragma unroll
            for (int r = 0; r < 8; r++) {
                acc[r].x += hh[r] * rv.x;
                acc[r].y += hh[r] * rv.y;
                acc[r].z += hh[r] * rv.z;
                acc[r].w += hh[r] * rv.w;
            }
        }
        // Store partials
        float* zp = z_s + ks * (8 * 128) + col4;
#pragma unroll
        for (int r = 0; r < 8; r++) *(float4*)(zp + r * 128) = acc[r];
        __syncthreads();

        // Gate + state update (threads 0..255)
        if (tid < 256) {
            float vi = xw0, vf = xw1, vg = xw2, vo = xw3;
#pragma unroll
            for (int sl = 0; sl < NSL; sl++) {
                const float* q = z_s + (sl * 8 + gr) * 128 + gc;
                vi += q[0];
                vf += q[32];
                vg += q[64];
                vo += q[96];
            }
            c_reg = fsig(vf) * c_reg + fsig(vi) * ftanh_(vg);
            const float hv = fsig(vo) * ftanh_(c_reg);
            g_h[(((size_t)dir * B_ + (b0 + gr)) * T_ + t) * H_ + cell0 + gc] = hv;
            stage[gr * 36 + gc] = hv;
        }
        __syncthreads();

        // Push h (transposed) to 4 cluster CTAs per thread; conflict-free.
        {
            const float v = stage[pr * 36 + pcg];
            const uint32_t off = hbase
                + (uint32_t)(((buf ^ 1) * 2048 + cell0 * 8 + j) * 4);
#pragma unroll
            for (int d = 0; d < 4; d++) {
                uint32_t ra;
                asm volatile("mapa.shared::cluster.u32 %0, %1, %2;"
                             : "=r"(ra) : "r"(off), "r"(dst0 + d));
                asm volatile("st.shared::cluster.f32 [%0], %1;"
                             :: "r"(ra), "f"(v));
            }
        }
        asm volatile("barrier.cluster.arrive.aligned;" ::: "memory");
        asm volatile("barrier.cluster.wait.aligned;" ::: "memory");
    }
}

// ---------------------------------------------------------------------------
// Phase C: attention pooling. One block (256 thr) per batch row.
// ---------------------------------------------------------------------------
__global__ __launch_bounds__(256) void attn_kernel(const float* __restrict__ att_w,
                                                   float* __restrict__ out)
{
    __shared__ float logits[T_];
    __shared__ float aw[H_];
    __shared__ float red[8];
    const int b = blockIdx.x;
    const int tid = threadIdx.x;
    const int warp = tid >> 5, lane = tid & 31;

    for (int i = tid; i < H_; i += 256) aw[i] = att_w[i];
    __syncthreads();

    const float* hf  = g_h + (size_t)b * T_ * H_;
    const float* hbp = g_h + ((size_t)B_ + b) * T_ * H_;

    for (int t = warp; t < T_; t += 8) {
        float s = 0.f;
        const float* pf = hf + (size_t)t * H_;
        const float* pb = hbp + (size_t)t * H_;
#pragma unroll
        for (int jj = 0; jj < 8; jj++) {
            int c = lane + 32 * jj;
            s += aw[c] * ftanh_(pf[c] + pb[c]);
        }
#pragma unroll
        for (int o = 16; o > 0; o >>= 1) s += __shfl_xor_sync(0xFFFFFFFFu, s, o);
        if (lane == 0) logits[t] = s;
    }
    __syncthreads();

    float m = -1e30f;
    for (int t = tid; t < T_; t += 256) m = fmaxf(m, logits[t]);
#pragma unroll
    for (int o = 16; o > 0; o >>= 1) m = fmaxf(m, __shfl_xor_sync(0xFFFFFFFFu, m, o));
    if (lane == 0) red[warp] = m;
    __syncthreads();
    float mg = red[0];
#pragma unroll
    for (int i = 1; i < 8; i++) mg = fmaxf(mg, red[i]);
    __syncthreads();

    float ssum = 0.f;
    for (int t = tid; t < T_; t += 256) {
        float e = __expf(logits[t] - mg);
        logits[t] = e;
        ssum += e;
    }
#pragma unroll
    for (int o = 16; o > 0; o >>= 1) ssum += __shfl_xor_sync(0xFFFFFFFFu, ssum, o);
    if (lane == 0) red[warp] = ssum;
    __syncthreads();
    float stot = 0.f;
#pragma unroll
    for (int i = 0; i < 8; i++) stot += red[i];
    const float inv = 1.0f / stot;
    __syncthreads();

    const int col = tid;
    float r = 0.f;
    for (int t = 0; t < T_; t++) {
        r += logits[t] * (hf[(size_t)t * H_ + col] + hbp[(size_t)t * H_ + col]);
    }
    out[b * H_ + col] = ftanh_(r * inv);
}

// ---------------------------------------------------------------------------
extern "C" void kernel_launch(void* const* d_in, const int* in_sizes, int n_in,
                              void* d_out, int out_size) {
    (void)in_sizes; (void)n_in; (void)out_size;
    const float* x     = (const float*)d_in[0];
    const float* k_fwd = (const float*)d_in[1];
    const float* r_fwd = (const float*)d_in[2];
    const float* b_fwd = (const float*)d_in[3];
    const float* k_bwd = (const float*)d_in[4];
    const float* r_bwd = (const float*)d_in[5];
    const float* b_bwd = (const float*)d_in[6];
    const float* att_w = (const float*)d_in[7];
    float* out = (float*)d_out;

    gemm_xw_kernel<<<dim3(16, 1024), 256>>>(x, k_fwd, b_fwd, k_bwd, b_bwd);

    cudaFuncSetAttribute(lstm_rec_kernel,
                         cudaFuncAttributeMaxDynamicSharedMemorySize, SMEM_B_BYTES);
    lstm_rec_kernel<<<dim3(8, 16), 512, SMEM_B_BYTES>>>(r_fwd, r_bwd);

    attn_kernel<<<B_, 256>>>(att_w, out);
}